// round 13
// baseline (speedup 1.0000x reference)
#include <cuda_runtime.h>

typedef unsigned long long u64;

#define NCTA 128
#define NTHR 256
#define B_   32
#define S_   1024
#define IN_  128
#define H_   512
#define OUT_ 128

// ---------------- device scratch (static __device__ arrays: allowed) --------
__device__ unsigned g_count;                       // grid-barrier counter
__device__ float g_xt[S_ * IN_ * B_];              // x transposed [t][i][b]   16MB
__device__ float g_h[3][H_ * B_];                  // hidden state [l][k][b]
__device__ float g_rh[H_ * B_];                    // r*h exchange [k][b]
__device__ float g_hist[(size_t)S_ * H_ * B_];     // last-layer h [t][k][b]   64MB

// ---------------- SMEM layout (u64 units) -----------------------------------
// duplicated-weight slices {w,w} so fma.rn.f32x2 needs no per-use packing
#define WXZ 0
#define WXR 2048
#define WXG 4096
#define WHZ 6144
#define WHR 8192
#define WHG 10240
#define W0Z 12288
#define W0R 12800
#define W0G 13312
#define RED 13824            // 3072 u64 partial-sum buffer
#define SM64_TOTAL 16896
#define SMEM_BYTES (SM64_TOTAL * 8 + 512 * 4)   // + float tail (sz/sg/sh/bias)

__device__ __forceinline__ void fma2(u64& c, u64 a, u64 b) {
    asm("fma.rn.f32x2 %0, %1, %2, %0;" : "+l"(c) : "l"(a), "l"(b));
}
__device__ __forceinline__ u64 ldcg2(const float2* p) {
    float2 v = __ldcg(p);
    u64 u;
    asm("mov.b64 %0, {%1, %2};" : "=l"(u) : "f"(v.x), "f"(v.y));
    return u;
}

// release/acquire all-CTA barrier (all 128 CTAs co-resident by construction)
__device__ __forceinline__ void grid_barrier(unsigned& target) {
    __syncthreads();
    if (threadIdx.x == 0) {
        target += NCTA;
        __threadfence();
        atomicAdd(&g_count, 1u);
        while (*(volatile unsigned*)&g_count < target) { }
        __threadfence();
    }
    __syncthreads();
}

// ---------------- init: reset barrier counter, transpose h0 -----------------
__global__ void init_kernel(const float* __restrict__ h0) {
    int idx = blockIdx.x * blockDim.x + threadIdx.x;
    if (idx == 0) g_count = 0;
    if (idx < 3 * H_ * B_) {
        int b = idx & 31;
        int k = (idx >> 5) & 511;
        int l = idx >> 14;
        g_h[l][k * 32 + b] = h0[b * (3 * H_) + l * H_ + k];
    }
}

// ---------------- transpose x: [b][t][i] -> [t][i][b] -----------------------
__global__ void transpose_x_kernel(const float* __restrict__ x) {
    __shared__ float tile[32 * 33];
    int t  = blockIdx.x >> 2;
    int i0 = (blockIdx.x & 3) * 32;
    int tid = threadIdx.x;
    int ii = tid & 31, jj = tid >> 5;
    for (int b = jj; b < 32; b += 8)
        tile[b * 33 + ii] = x[((size_t)b * S_ + t) * IN_ + i0 + ii];
    __syncthreads();
    int bb = tid & 31, ir = tid >> 5;
    for (int i = ir; i < 32; i += 8)
        g_xt[(t * IN_ + i0 + i) * B_ + bb] = tile[bb * 33 + i];
}

// ---------------- the persistent GRU kernel ---------------------------------
__global__ void __launch_bounds__(NTHR, 1) gru_persistent(
    const float* __restrict__ W0z, const float* __restrict__ b0z,
    const float* __restrict__ W0r, const float* __restrict__ b0r,
    const float* __restrict__ W0g, const float* __restrict__ b0g,
    const float* __restrict__ Wxz, const float* __restrict__ bxz,
    const float* __restrict__ Wxr, const float* __restrict__ bxr,
    const float* __restrict__ Wxg, const float* __restrict__ bxg,
    const float* __restrict__ Whz, const float* __restrict__ Whr,
    const float* __restrict__ Whg)
{
    extern __shared__ u64 sm64[];
    float* tail = (float*)(sm64 + SM64_TOTAL);
    float* s_z = tail;            // [4][32] z values
    float* s_g = tail + 128;      // [4][32] xg + bias
    float* s_h = tail + 256;      // [4][32] old h
    float* s_b = tail + 384;      // biases [6][4]

    const int tid  = threadIdx.x;
    const int row0 = blockIdx.x * 4;

    // ---- load duplicated weight slices (once per launch) ----
    float2* w2 = (float2*)sm64;
    for (int idx = tid; idx < 2048; idx += NTHR) {
        int r = idx >> 9, k = idx & 511;
        int g = (row0 + r) * H_ + k;
        float w;
        w = Wxz[g]; w2[WXZ + idx] = make_float2(w, w);
        w = Wxr[g]; w2[WXR + idx] = make_float2(w, w);
        w = Wxg[g]; w2[WXG + idx] = make_float2(w, w);
        w = Whz[g]; w2[WHZ + idx] = make_float2(w, w);
        w = Whr[g]; w2[WHR + idx] = make_float2(w, w);
        w = Whg[g]; w2[WHG + idx] = make_float2(w, w);
    }
    for (int idx = tid; idx < 512; idx += NTHR) {
        int r = idx >> 7, k = idx & 127;
        int g = (row0 + r) * IN_ + k;
        float w;
        w = W0z[g]; w2[W0Z + idx] = make_float2(w, w);
        w = W0r[g]; w2[W0R + idx] = make_float2(w, w);
        w = W0g[g]; w2[W0G + idx] = make_float2(w, w);
    }
    if (tid < 4) {
        s_b[0 * 4 + tid] = b0z[row0 + tid];
        s_b[1 * 4 + tid] = b0r[row0 + tid];
        s_b[2 * 4 + tid] = b0g[row0 + tid];
        s_b[3 * 4 + tid] = bxz[row0 + tid];
        s_b[4 * 4 + tid] = bxr[row0 + tid];
        s_b[5 * 4 + tid] = bxg[row0 + tid];
    }
    __syncthreads();

    const int bp = tid & 15;   // batch pair: covers b = 2bp, 2bp+1
    const int ks = tid >> 4;   // k-slice 0..15 (32 hidden k / 8 input k each)
    u64* red = sm64 + RED;
    unsigned target = 0;

    for (int t = 0; t < S_; t++) {
        for (int l = 0; l < 3; l++) {
            // ================= phase A: z/r full dots + xg input dot ========
            u64 az[4], ar[4], ag[4];
#pragma unroll
            for (int r = 0; r < 4; r++) { az[r] = 0ull; ar[r] = 0ull; ag[r] = 0ull; }

            if (l == 0) {
                const float2* xin = (const float2*)(g_xt + t * (IN_ * B_));
                const float2* hin = (const float2*)(g_h[0]);
                int kin = ks * 8;
#pragma unroll
                for (int kk = 0; kk < 8; kk += 2) {
                    int k = kin + kk;
                    u64 x0 = ldcg2(xin + k * 16 + bp);
                    u64 x1 = ldcg2(xin + (k + 1) * 16 + bp);
#pragma unroll
                    for (int r = 0; r < 4; r++) {
                        fma2(az[r], x0, sm64[W0Z + r * 128 + k]);
                        fma2(az[r], x1, sm64[W0Z + r * 128 + k + 1]);
                        fma2(ar[r], x0, sm64[W0R + r * 128 + k]);
                        fma2(ar[r], x1, sm64[W0R + r * 128 + k + 1]);
                        fma2(ag[r], x0, sm64[W0G + r * 128 + k]);
                        fma2(ag[r], x1, sm64[W0G + r * 128 + k + 1]);
                    }
                }
                int kh = ks * 32;
#pragma unroll 4
                for (int kk = 0; kk < 32; kk += 2) {
                    int k = kh + kk;
                    u64 h0v = ldcg2(hin + k * 16 + bp);
                    u64 h1v = ldcg2(hin + (k + 1) * 16 + bp);
#pragma unroll
                    for (int r = 0; r < 4; r++) {
                        fma2(az[r], h0v, sm64[WHZ + r * 512 + k]);
                        fma2(az[r], h1v, sm64[WHZ + r * 512 + k + 1]);
                        fma2(ar[r], h0v, sm64[WHR + r * 512 + k]);
                        fma2(ar[r], h1v, sm64[WHR + r * 512 + k + 1]);
                    }
                }
            } else {
                const float2* xin = (const float2*)(g_h[l - 1]);
                const float2* hin = (const float2*)(g_h[l]);
                int kh = ks * 32;
#pragma unroll 4
                for (int kk = 0; kk < 32; kk += 2) {
                    int k = kh + kk;
                    u64 x0  = ldcg2(xin + k * 16 + bp);
                    u64 x1  = ldcg2(xin + (k + 1) * 16 + bp);
                    u64 h0v = ldcg2(hin + k * 16 + bp);
                    u64 h1v = ldcg2(hin + (k + 1) * 16 + bp);
#pragma unroll
                    for (int r = 0; r < 4; r++) {
                        fma2(az[r], x0,  sm64[WXZ + r * 512 + k]);
                        fma2(az[r], x1,  sm64[WXZ + r * 512 + k + 1]);
                        fma2(ar[r], x0,  sm64[WXR + r * 512 + k]);
                        fma2(ar[r], x1,  sm64[WXR + r * 512 + k + 1]);
                        fma2(ag[r], x0,  sm64[WXG + r * 512 + k]);
                        fma2(ag[r], x1,  sm64[WXG + r * 512 + k + 1]);
                        fma2(az[r], h0v, sm64[WHZ + r * 512 + k]);
                        fma2(az[r], h1v, sm64[WHZ + r * 512 + k + 1]);
                        fma2(ar[r], h0v, sm64[WHR + r * 512 + k]);
                        fma2(ar[r], h1v, sm64[WHR + r * 512 + k + 1]);
                    }
                }
            }
#pragma unroll
            for (int r = 0; r < 4; r++) {
                red[(0 * 16 + ks) * 64 + r * 16 + bp] = az[r];
                red[(1 * 16 + ks) * 64 + r * 16 + bp] = ar[r];
                red[(2 * 16 + ks) * 64 + r * 16 + bp] = ag[r];
            }
            __syncthreads();

            // ---- reduce A: z, r, stash xg; publish r*h ----
            if (tid < 128) {
                int r = tid >> 5, b = tid & 31;
                const float* rf = (const float*)red;
                float sz_ = 0.f, sr_ = 0.f, sg_ = 0.f;
#pragma unroll
                for (int q = 0; q < 16; q++) {
                    sz_ += rf[(0 * 16 + q) * 128 + r * 32 + b];
                    sr_ += rf[(1 * 16 + q) * 128 + r * 32 + b];
                    sg_ += rf[(2 * 16 + q) * 128 + r * 32 + b];
                }
                int bb = (l == 0) ? 0 : 3;
                float zv = 1.f / (1.f + expf(-(sz_ + s_b[bb * 4 + r])));
                float rv = 1.f / (1.f + expf(-(sr_ + s_b[(bb + 1) * 4 + r])));
                float hold = __ldcg(&g_h[l][(row0 + r) * 32 + b]);
                g_rh[(row0 + r) * 32 + b] = rv * hold;
                s_z[tid] = zv;
                s_g[tid] = sg_ + s_b[(bb + 2) * 4 + r];
                s_h[tid] = hold;
            }
            grid_barrier(target);

            // ================= phase B: (r*h) @ Whg^T =======================
            {
                u64 agg[4] = {0ull, 0ull, 0ull, 0ull};
                const float2* rin = (const float2*)g_rh;
                int kh = ks * 32;
#pragma unroll 4
                for (int kk = 0; kk < 32; kk += 2) {
                    int k = kh + kk;
                    u64 v0 = ldcg2(rin + k * 16 + bp);
                    u64 v1 = ldcg2(rin + (k + 1) * 16 + bp);
#pragma unroll
                    for (int r = 0; r < 4; r++) {
                        fma2(agg[r], v0, sm64[WHG + r * 512 + k]);
                        fma2(agg[r], v1, sm64[WHG + r * 512 + k + 1]);
                    }
                }
#pragma unroll
                for (int r = 0; r < 4; r++)
                    red[ks * 64 + r * 16 + bp] = agg[r];
            }
            __syncthreads();

            // ---- reduce B: g, h_new ----
            if (tid < 128) {
                int r = tid >> 5, b = tid & 31;
                const float* rf = (const float*)red;
                float s = 0.f;
#pragma unroll
                for (int q = 0; q < 16; q++)
                    s += rf[q * 128 + r * 32 + b];
                float gv = tanhf(s_g[tid] + s);
                float hn = fmaf(s_z[tid], s_h[tid] - gv, gv);   // z*h + (1-z)*g
                g_h[l][(row0 + r) * 32 + b] = hn;
                if (l == 2)
                    g_hist[(size_t)t * (H_ * B_) + (row0 + r) * 32 + b] = hn;
            }
            grid_barrier(target);
        }
    }
}

// ---------------- epilogue: out = hist @ Wout^T + bout ----------------------
__global__ void __launch_bounds__(256) out_proj_kernel(
    const float* __restrict__ Wout, const float* __restrict__ bout,
    float* __restrict__ out)
{
    extern __shared__ float sh[];   // 512*32 floats (64 KB): hist[t]
    int t = blockIdx.x;
    int tid = threadIdx.x;
    const float* src = g_hist + (size_t)t * (H_ * B_);
    for (int j = tid; j < (H_ * B_) / 4; j += 256)
        ((float4*)sh)[j] = ((const float4*)src)[j];
    __syncthreads();

    int o0 = (tid >> 3) * 4;   // 4 output channels
    int b0 = (tid & 7) * 4;    // 4 batches
    float acc[4][4];
#pragma unroll
    for (int i = 0; i < 4; i++)
#pragma unroll
        for (int j = 0; j < 4; j++) acc[i][j] = 0.f;

    for (int k = 0; k < H_; k += 4) {
        float4 h0 = *(const float4*)&sh[(k + 0) * 32 + b0];
        float4 h1 = *(const float4*)&sh[(k + 1) * 32 + b0];
        float4 h2 = *(const float4*)&sh[(k + 2) * 32 + b0];
        float4 h3 = *(const float4*)&sh[(k + 3) * 32 + b0];
#pragma unroll
        for (int i = 0; i < 4; i++) {
            float4 w = __ldg((const float4*)&Wout[(o0 + i) * H_ + k]);
            acc[i][0] = fmaf(w.x, h0.x, acc[i][0]);
            acc[i][0] = fmaf(w.y, h1.x, acc[i][0]);
            acc[i][0] = fmaf(w.z, h2.x, acc[i][0]);
            acc[i][0] = fmaf(w.w, h3.x, acc[i][0]);
            acc[i][1] = fmaf(w.x, h0.y, acc[i][1]);
            acc[i][1] = fmaf(w.y, h1.y, acc[i][1]);
            acc[i][1] = fmaf(w.z, h2.y, acc[i][1]);
            acc[i][1] = fmaf(w.w, h3.y, acc[i][1]);
            acc[i][2] = fmaf(w.x, h0.z, acc[i][2]);
            acc[i][2] = fmaf(w.y, h1.z, acc[i][2]);
            acc[i][2] = fmaf(w.z, h2.z, acc[i][2]);
            acc[i][2] = fmaf(w.w, h3.z, acc[i][2]);
            acc[i][3] = fmaf(w.x, h0.w, acc[i][3]);
            acc[i][3] = fmaf(w.y, h1.w, acc[i][3]);
            acc[i][3] = fmaf(w.z, h2.w, acc[i][3]);
            acc[i][3] = fmaf(w.w, h3.w, acc[i][3]);
        }
    }
#pragma unroll
    for (int j = 0; j < 4; j++)
#pragma unroll
        for (int i = 0; i < 4; i++)
            out[((size_t)(b0 + j) * S_ + t) * OUT_ + o0 + i] =
                acc[i][j] + __ldg(&bout[o0 + i]);
}

// ---------------- epilogue: final hidden state (B, L, H) --------------------
__global__ void final_state_kernel(float* __restrict__ out2) {
    int idx = blockIdx.x * blockDim.x + threadIdx.x;
    if (idx < 3 * H_ * B_) {
        int k = idx & 511;
        int v = idx >> 9;        // b*3 + l
        int l = v % 3;
        int b = v / 3;
        out2[idx] = g_h[l][k * 32 + b];
    }
}

// ---------------- launch ----------------------------------------------------
extern "C" void kernel_launch(void* const* d_in, const int* in_sizes, int n_in,
                              void* d_out, int out_size) {
    const float* x    = (const float*)d_in[0];
    const float* h0   = (const float*)d_in[1];
    const float* W0z  = (const float*)d_in[2];
    const float* b0z  = (const float*)d_in[3];
    const float* W0r  = (const float*)d_in[4];
    const float* b0r  = (const float*)d_in[5];
    const float* W0g  = (const float*)d_in[6];
    const float* b0g  = (const float*)d_in[7];
    const float* Wxz  = (const float*)d_in[8];
    const float* bxz  = (const float*)d_in[9];
    const float* Wxr  = (const float*)d_in[10];
    const float* bxr  = (const float*)d_in[11];
    const float* Wxg  = (const float*)d_in[12];
    const float* bxg  = (const float*)d_in[13];
    const float* Whz  = (const float*)d_in[14];
    const float* Whr  = (const float*)d_in[15];
    const float* Whg  = (const float*)d_in[16];
    const float* Wout = (const float*)d_in[17];
    const float* bout = (const float*)d_in[18];
    float* out = (float*)d_out;

    cudaFuncSetAttribute(gru_persistent,
                         cudaFuncAttributeMaxDynamicSharedMemorySize, SMEM_BYTES);
    cudaFuncSetAttribute(out_proj_kernel,
                         cudaFuncAttributeMaxDynamicSharedMemorySize, 65536);

    init_kernel<<<192, 256>>>(h0);
    transpose_x_kernel<<<S_ * 4, 256>>>(x);
    gru_persistent<<<NCTA, NTHR, SMEM_BYTES>>>(
        W0z, b0z, W0r, b0r, W0g, b0g,
        Wxz, bxz, Wxr, bxr, Wxg, bxg,
        Whz, Whr, Whg);
    out_proj_kernel<<<S_, 256, 65536>>>(Wout, bout, out);
    final_state_kernel<<<192, 256>>>(out + (size_t)B_ * S_ * OUT_);
}

// round 14
// speedup vs baseline: 1.1850x; 1.1850x over previous
#include <cuda_runtime.h>

typedef unsigned long long u64;

#define NCTA 128
#define NTHR 256
#define B_   32
#define S_   1024
#define IN_  128
#define H_   512
#define OUT_ 128

// ---------------- device scratch (static __device__ arrays: allowed) --------
__device__ unsigned g_count;                                   // barrier counter
__device__ __align__(128) float g_xt[S_ * IN_ * B_];           // x^T [t][i][b] 16MB
__device__ __align__(128) float g_h[3][H_ * B_];               // state [l][k][b]
__device__ __align__(128) float g_rh[H_ * B_];                 // r*h  [k][b]
__device__ __align__(128) float g_hist[(size_t)S_ * H_ * B_];  // [t][k][b] 64MB

// ---------------- SMEM layout (u64 units) -----------------------------------
// weights duplicated {w,w}, laid out [mat][r][kk][ks] so the 4 in-warp ks
// values are 8B apart (conflict-free LDS.64 broadcast).
#define WXZ 0
#define WXR 2048
#define WXG 4096
#define WHZ 6144
#define WHR 8192
#define WHG 10240
#define W0Z 12288
#define W0R 12800
#define W0G 13312
#define RED 13824               // 1536 u64 partial buffer
#define SM64_TOTAL 15360
#define SMEM_BYTES (SM64_TOTAL * 8 + 408 * 4)

__device__ __forceinline__ void fma2(u64& c, u64 a, u64 b) {
    asm("fma.rn.f32x2 %0, %1, %2, %0;" : "+l"(c) : "l"(a), "l"(b));
}
__device__ __forceinline__ void add2(u64& c, u64 a) {
    asm("add.rn.f32x2 %0, %0, %1;" : "+l"(c) : "l"(a));
}
__device__ __forceinline__ void pack2(const float4 v, u64& lo, u64& hi) {
    asm("mov.b64 %0, {%1, %2};" : "=l"(lo) : "f"(v.x), "f"(v.y));
    asm("mov.b64 %0, {%1, %2};" : "=l"(hi) : "f"(v.z), "f"(v.w));
}
// reduce over the 4 in-warp ks sub-slices (lanes lane, lane^8, lane^16, lane^24)
__device__ __forceinline__ u64 ksred(u64 v) {
    add2(v, __shfl_xor_sync(0xffffffffu, v, 8));
    add2(v, __shfl_xor_sync(0xffffffffu, v, 16));
    return v;
}
__device__ __forceinline__ float sigf(float x) {
    return __fdividef(1.f, 1.f + __expf(-x));
}
__device__ __forceinline__ float tanhfast(float x) {
    return fmaf(2.f, __fdividef(1.f, 1.f + __expf(-2.f * x)), -1.f);
}

// all-CTA barrier (all 128 CTAs co-resident): fence + atomic arrive, spin+backoff
__device__ __forceinline__ void grid_barrier(unsigned& target) {
    __syncthreads();
    if (threadIdx.x == 0) {
        target += NCTA;
        __threadfence();
        atomicAdd(&g_count, 1u);
        while (*(volatile unsigned*)&g_count < target) __nanosleep(40);
        __threadfence();
    }
    __syncthreads();
}

// ---------------- init: reset barrier, transpose h0 -------------------------
__global__ void init_kernel(const float* __restrict__ h0) {
    int idx = blockIdx.x * blockDim.x + threadIdx.x;
    if (idx == 0) g_count = 0;
    if (idx < 3 * H_ * B_) {
        int b = idx & 31;
        int k = (idx >> 5) & 511;
        int l = idx >> 14;
        g_h[l][k * 32 + b] = h0[b * (3 * H_) + l * H_ + k];
    }
}

// ---------------- transpose x: [b][t][i] -> [t][i][b] -----------------------
__global__ void transpose_x_kernel(const float* __restrict__ x) {
    __shared__ float tile[32 * 33];
    int t  = blockIdx.x >> 2;
    int i0 = (blockIdx.x & 3) * 32;
    int tid = threadIdx.x;
    int ii = tid & 31, jj = tid >> 5;
    for (int b = jj; b < 32; b += 8)
        tile[b * 33 + ii] = x[((size_t)b * S_ + t) * IN_ + i0 + ii];
    __syncthreads();
    int bb = tid & 31, ir = tid >> 5;
    for (int i = ir; i < 32; i += 8)
        g_xt[(t * IN_ + i0 + i) * B_ + bb] = tile[bb * 33 + i];
}

// ---------------- persistent GRU kernel --------------------------------------
__global__ void __launch_bounds__(NTHR, 1) gru_persistent(
    const float* __restrict__ W0z, const float* __restrict__ b0z,
    const float* __restrict__ W0r, const float* __restrict__ b0r,
    const float* __restrict__ W0g, const float* __restrict__ b0g,
    const float* __restrict__ Wxz, const float* __restrict__ bxz,
    const float* __restrict__ Wxr, const float* __restrict__ bxr,
    const float* __restrict__ Wxg, const float* __restrict__ bxg,
    const float* __restrict__ Whz, const float* __restrict__ Whr,
    const float* __restrict__ Whg)
{
    extern __shared__ u64 sm64[];
    float* tail = (float*)(sm64 + SM64_TOTAL);
    float* s_z = tail;            // [4][32]
    float* s_g = tail + 128;      // [4][32]
    float* s_h = tail + 256;      // [4][32]
    float* s_b = tail + 384;      // [6][4]

    const int tid  = threadIdx.x;
    const int row0 = blockIdx.x * 4;

    // ---- load duplicated weight slices, layout [r][kk][ks] ----
    float2* w2 = (float2*)sm64;
    for (int idx = tid; idx < 2048; idx += NTHR) {
        int r = idx >> 9, kk = (idx >> 5) & 15, kq = idx & 31;
        int g = (row0 + r) * H_ + kq * 16 + kk;
        float w;
        w = Wxz[g]; w2[WXZ + idx] = make_float2(w, w);
        w = Wxr[g]; w2[WXR + idx] = make_float2(w, w);
        w = Wxg[g]; w2[WXG + idx] = make_float2(w, w);
        w = Whz[g]; w2[WHZ + idx] = make_float2(w, w);
        w = Whr[g]; w2[WHR + idx] = make_float2(w, w);
        w = Whg[g]; w2[WHG + idx] = make_float2(w, w);
    }
    for (int idx = tid; idx < 512; idx += NTHR) {
        int r = idx >> 7, kk = (idx >> 5) & 3, kq = idx & 31;
        int g = (row0 + r) * IN_ + kq * 4 + kk;
        float w;
        w = W0z[g]; w2[W0Z + idx] = make_float2(w, w);
        w = W0r[g]; w2[W0R + idx] = make_float2(w, w);
        w = W0g[g]; w2[W0G + idx] = make_float2(w, w);
    }
    if (tid < 4) {
        s_b[0 * 4 + tid] = b0z[row0 + tid];
        s_b[1 * 4 + tid] = b0r[row0 + tid];
        s_b[2 * 4 + tid] = b0g[row0 + tid];
        s_b[3 * 4 + tid] = bxz[row0 + tid];
        s_b[4 * 4 + tid] = bxr[row0 + tid];
        s_b[5 * 4 + tid] = bxg[row0 + tid];
    }
    __syncthreads();

    const int bp   = tid & 7;     // batch quad: b = 4bp .. 4bp+3
    const int ks   = tid >> 3;    // k-slice 0..31 (16 hidden k / 4 input k)
    const int warp = tid >> 5;
    const int lane = tid & 31;
    const int kb   = ks * 16;     // hidden k base
    const int kbi  = ks * 4;      // input k base
    u64* red = sm64 + RED;
    unsigned target = 0;

    for (int t = 0; t < S_; t++) {
        for (int l = 0; l < 3; l++) {
            // ============ phase A: z/r full dots + xg input-side dot =========
            u64 az[4][2], ar[4][2], ag[4][2];
#pragma unroll
            for (int r = 0; r < 4; r++) {
                az[r][0] = az[r][1] = 0ull;
                ar[r][0] = ar[r][1] = 0ull;
                ag[r][0] = ag[r][1] = 0ull;
            }

            if (l == 0) {
                // input part (IN=128): 4 kk, all preloaded
                const float4* xin4 = (const float4*)(g_xt + t * (IN_ * B_));
                float4 pfx[4];
#pragma unroll
                for (int kk = 0; kk < 4; kk++)
                    pfx[kk] = __ldcg(xin4 + (kbi + kk) * 8 + bp);
#pragma unroll
                for (int kk = 0; kk < 4; kk++) {
                    u64 x0, x1;
                    pack2(pfx[kk], x0, x1);
#pragma unroll
                    for (int r = 0; r < 4; r++) {
                        int wi = ((r * 4 + kk) << 5) + ks;
                        u64 wz = sm64[W0Z + wi], wr = sm64[W0R + wi], wg = sm64[W0G + wi];
                        fma2(az[r][0], x0, wz); fma2(az[r][1], x1, wz);
                        fma2(ar[r][0], x0, wr); fma2(ar[r][1], x1, wr);
                        fma2(ag[r][0], x0, wg); fma2(ag[r][1], x1, wg);
                    }
                }
                // hidden part (H=512): Whz, Whr
                const float4* hin4 = (const float4*)(g_h[0]);
                float4 pfh[2];
                pfh[0] = __ldcg(hin4 + (kb + 0) * 8 + bp);
                pfh[1] = __ldcg(hin4 + (kb + 1) * 8 + bp);
#pragma unroll
                for (int kk = 0; kk < 16; kk++) {
                    u64 h0, h1;
                    pack2(pfh[kk & 1], h0, h1);
                    if (kk < 14)
                        pfh[kk & 1] = __ldcg(hin4 + (kb + kk + 2) * 8 + bp);
#pragma unroll
                    for (int r = 0; r < 4; r++) {
                        int wi = ((r * 16 + kk) << 5) + ks;
                        u64 wz = sm64[WHZ + wi], wr = sm64[WHR + wi];
                        fma2(az[r][0], h0, wz); fma2(az[r][1], h1, wz);
                        fma2(ar[r][0], h0, wr); fma2(ar[r][1], h1, wr);
                    }
                }
            } else {
                const float4* xin4 = (const float4*)(g_h[l - 1]);
                const float4* hin4 = (const float4*)(g_h[l]);
                float4 pfx[2], pfh[2];
                pfx[0] = __ldcg(xin4 + (kb + 0) * 8 + bp);
                pfh[0] = __ldcg(hin4 + (kb + 0) * 8 + bp);
                pfx[1] = __ldcg(xin4 + (kb + 1) * 8 + bp);
                pfh[1] = __ldcg(hin4 + (kb + 1) * 8 + bp);
#pragma unroll
                for (int kk = 0; kk < 16; kk++) {
                    u64 x0, x1, h0, h1;
                    pack2(pfx[kk & 1], x0, x1);
                    pack2(pfh[kk & 1], h0, h1);
                    if (kk < 14) {
                        pfx[kk & 1] = __ldcg(xin4 + (kb + kk + 2) * 8 + bp);
                        pfh[kk & 1] = __ldcg(hin4 + (kb + kk + 2) * 8 + bp);
                    }
#pragma unroll
                    for (int r = 0; r < 4; r++) {
                        int wi = ((r * 16 + kk) << 5) + ks;
                        u64 wxzv = sm64[WXZ + wi], wxrv = sm64[WXR + wi];
                        u64 wxgv = sm64[WXG + wi];
                        u64 whzv = sm64[WHZ + wi], whrv = sm64[WHR + wi];
                        fma2(az[r][0], x0, wxzv); fma2(az[r][1], x1, wxzv);
                        fma2(ar[r][0], x0, wxrv); fma2(ar[r][1], x1, wxrv);
                        fma2(ag[r][0], x0, wxgv); fma2(ag[r][1], x1, wxgv);
                        fma2(az[r][0], h0, whzv); fma2(az[r][1], h1, whzv);
                        fma2(ar[r][0], h0, whrv); fma2(ar[r][1], h1, whrv);
                    }
                }
            }
            // in-warp pre-reduction over 4 ks sub-slices, then STS (lanes 0..7)
#pragma unroll
            for (int r = 0; r < 4; r++) {
                u64 vz0 = ksred(az[r][0]), vz1 = ksred(az[r][1]);
                u64 vr0 = ksred(ar[r][0]), vr1 = ksred(ar[r][1]);
                u64 vg0 = ksred(ag[r][0]), vg1 = ksred(ag[r][1]);
                if (lane < 8) {
                    int base = (((0 * 8 + warp) * 4 + r) * 8 + bp) * 2;
                    red[base] = vz0; red[base + 1] = vz1;
                    base = (((1 * 8 + warp) * 4 + r) * 8 + bp) * 2;
                    red[base] = vr0; red[base + 1] = vr1;
                    base = (((2 * 8 + warp) * 4 + r) * 8 + bp) * 2;
                    red[base] = vg0; red[base + 1] = vg1;
                }
            }
            __syncthreads();

            // ---- reduce A: z, r; stash xg; publish r*h ----
            if (tid < 128) {
                int r = tid >> 5, b = tid & 31;
                const float* rf = (const float*)red;
                float sz_ = 0.f, sr_ = 0.f, sg_ = 0.f;
#pragma unroll
                for (int w = 0; w < 8; w++) {
                    sz_ += rf[(0 * 8 + w) * 128 + r * 32 + b];
                    sr_ += rf[(1 * 8 + w) * 128 + r * 32 + b];
                    sg_ += rf[(2 * 8 + w) * 128 + r * 32 + b];
                }
                int bb = (l == 0) ? 0 : 3;
                float zv = sigf(sz_ + s_b[bb * 4 + r]);
                float rv = sigf(sr_ + s_b[(bb + 1) * 4 + r]);
                float hold = __ldcg(&g_h[l][(row0 + r) * 32 + b]);
                __stcg(&g_rh[(row0 + r) * 32 + b], rv * hold);
                s_z[tid] = zv;
                s_g[tid] = sg_ + s_b[(bb + 2) * 4 + r];
                s_h[tid] = hold;
            }
            grid_barrier(target);

            // ============ phase B: (r*h) @ Whg^T =============================
            {
                u64 agg[4][2];
#pragma unroll
                for (int r = 0; r < 4; r++) agg[r][0] = agg[r][1] = 0ull;
                const float4* rin4 = (const float4*)g_rh;
                float4 pfr[2];
                pfr[0] = __ldcg(rin4 + (kb + 0) * 8 + bp);
                pfr[1] = __ldcg(rin4 + (kb + 1) * 8 + bp);
#pragma unroll
                for (int kk = 0; kk < 16; kk++) {
                    u64 v0, v1;
                    pack2(pfr[kk & 1], v0, v1);
                    if (kk < 14)
                        pfr[kk & 1] = __ldcg(rin4 + (kb + kk + 2) * 8 + bp);
#pragma unroll
                    for (int r = 0; r < 4; r++) {
                        u64 wg = sm64[WHG + ((r * 16 + kk) << 5) + ks];
                        fma2(agg[r][0], v0, wg); fma2(agg[r][1], v1, wg);
                    }
                }
#pragma unroll
                for (int r = 0; r < 4; r++) {
                    u64 v0 = ksred(agg[r][0]), v1 = ksred(agg[r][1]);
                    if (lane < 8) {
                        int base = ((warp * 4 + r) * 8 + bp) * 2;
                        red[base] = v0; red[base + 1] = v1;
                    }
                }
            }
            __syncthreads();

            // ---- reduce B: g, h_new ----
            if (tid < 128) {
                int r = tid >> 5, b = tid & 31;
                const float* rf = (const float*)red;
                float s = 0.f;
#pragma unroll
                for (int w = 0; w < 8; w++)
                    s += rf[w * 128 + r * 32 + b];
                float gv = tanhfast(s_g[tid] + s);
                float hn = fmaf(s_z[tid], s_h[tid] - gv, gv);
                __stcg(&g_h[l][(row0 + r) * 32 + b], hn);
                if (l == 2)
                    g_hist[(size_t)t * (H_ * B_) + (row0 + r) * 32 + b] = hn;
            }
            grid_barrier(target);
        }
    }
}

// ---------------- epilogue: out = hist @ Wout^T + bout ----------------------
__global__ void __launch_bounds__(256) out_proj_kernel(
    const float* __restrict__ Wout, const float* __restrict__ bout,
    float* __restrict__ out)
{
    extern __shared__ float sh[];   // 64 KB: hist[t]
    int t = blockIdx.x;
    int tid = threadIdx.x;
    const float* src = g_hist + (size_t)t * (H_ * B_);
    for (int j = tid; j < (H_ * B_) / 4; j += 256)
        ((float4*)sh)[j] = ((const float4*)src)[j];
    __syncthreads();

    int o0 = (tid >> 3) * 4;
    int b0 = (tid & 7) * 4;
    float acc[4][4];
#pragma unroll
    for (int i = 0; i < 4; i++)
#pragma unroll
        for (int j = 0; j < 4; j++) acc[i][j] = 0.f;

    for (int k = 0; k < H_; k += 4) {
        float4 h0 = *(const float4*)&sh[(k + 0) * 32 + b0];
        float4 h1 = *(const float4*)&sh[(k + 1) * 32 + b0];
        float4 h2 = *(const float4*)&sh[(k + 2) * 32 + b0];
        float4 h3 = *(const float4*)&sh[(k + 3) * 32 + b0];
#pragma unroll
        for (int i = 0; i < 4; i++) {
            float4 w = __ldg((const float4*)&Wout[(o0 + i) * H_ + k]);
            acc[i][0] = fmaf(w.x, h0.x, acc[i][0]);
            acc[i][0] = fmaf(w.y, h1.x, acc[i][0]);
            acc[i][0] = fmaf(w.z, h2.x, acc[i][0]);
            acc[i][0] = fmaf(w.w, h3.x, acc[i][0]);
            acc[i][1] = fmaf(w.x, h0.y, acc[i][1]);
            acc[i][1] = fmaf(w.y, h1.y, acc[i][1]);
            acc[i][1] = fmaf(w.z, h2.y, acc[i][1]);
            acc[i][1] = fmaf(w.w, h3.y, acc[i][1]);
            acc[i][2] = fmaf(w.x, h0.z, acc[i][2]);
            acc[i][2] = fmaf(w.y, h1.z, acc[i][2]);
            acc[i][2] = fmaf(w.z, h2.z, acc[i][2]);
            acc[i][2] = fmaf(w.w, h3.z, acc[i][2]);
            acc[i][3] = fmaf(w.x, h0.w, acc[i][3]);
            acc[i][3] = fmaf(w.y, h1.w, acc[i][3]);
            acc[i][3] = fmaf(w.z, h2.w, acc[i][3]);
            acc[i][3] = fmaf(w.w, h3.w, acc[i][3]);
        }
    }
#pragma unroll
    for (int j = 0; j < 4; j++)
#pragma unroll
        for (int i = 0; i < 4; i++)
            out[((size_t)(b0 + j) * S_ + t) * OUT_ + o0 + i] =
                acc[i][j] + __ldg(&bout[o0 + i]);
}

// ---------------- epilogue: final hidden state (B, L, H) --------------------
__global__ void final_state_kernel(float* __restrict__ out2) {
    int idx = blockIdx.x * blockDim.x + threadIdx.x;
    if (idx < 3 * H_ * B_) {
        int k = idx & 511;
        int v = idx >> 9;
        int l = v % 3;
        int b = v / 3;
        out2[idx] = g_h[l][k * 32 + b];
    }
}

// ---------------- launch ----------------------------------------------------
extern "C" void kernel_launch(void* const* d_in, const int* in_sizes, int n_in,
                              void* d_out, int out_size) {
    const float* x    = (const float*)d_in[0];
    const float* h0   = (const float*)d_in[1];
    const float* W0z  = (const float*)d_in[2];
    const float* b0z  = (const float*)d_in[3];
    const float* W0r  = (const float*)d_in[4];
    const float* b0r  = (const float*)d_in[5];
    const float* W0g  = (const float*)d_in[6];
    const float* b0g  = (const float*)d_in[7];
    const float* Wxz  = (const float*)d_in[8];
    const float* bxz  = (const float*)d_in[9];
    const float* Wxr  = (const float*)d_in[10];
    const float* bxr  = (const float*)d_in[11];
    const float* Wxg  = (const float*)d_in[12];
    const float* bxg  = (const float*)d_in[13];
    const float* Whz  = (const float*)d_in[14];
    const float* Whr  = (const float*)d_in[15];
    const float* Whg  = (const float*)d_in[16];
    const float* Wout = (const float*)d_in[17];
    const float* bout = (const float*)d_in[18];
    float* out = (float*)d_out;

    cudaFuncSetAttribute(gru_persistent,
                         cudaFuncAttributeMaxDynamicSharedMemorySize, SMEM_BYTES);
    cudaFuncSetAttribute(out_proj_kernel,
                         cudaFuncAttributeMaxDynamicSharedMemorySize, 65536);

    init_kernel<<<192, 256>>>(h0);
    transpose_x_kernel<<<S_ * 4, 256>>>(x);
    gru_persistent<<<NCTA, NTHR, SMEM_BYTES>>>(
        W0z, b0z, W0r, b0r, W0g, b0g,
        Wxz, bxz, Wxr, bxr, Wxg, bxg,
        Whz, Whr, Whg);
    out_proj_kernel<<<S_, 256, 65536>>>(Wout, bout, out);
    final_state_kernel<<<192, 256>>>(out + (size_t)B_ * S_ * OUT_);
}

// round 15
// speedup vs baseline: 1.2640x; 1.0667x over previous
#include <cuda_runtime.h>

typedef unsigned long long u64;

#define NCTA 128
#define NTHR 256
#define B_   32
#define S_   1024
#define IN_  128
#define H_   512
#define OUT_ 128

// ---------------- device scratch (static __device__ arrays: allowed) --------
__device__ unsigned g_count;                                   // barrier counter
__device__ __align__(128) float g_xt[S_ * IN_ * B_];           // x^T [t][i][b] 16MB
__device__ __align__(128) float g_h[3][H_ * B_];               // state [l][k][b]
__device__ __align__(128) float g_rh[H_ * B_];                 // r*h  [k][b]
__device__ __align__(128) float g_hist[(size_t)S_ * H_ * B_];  // [t][k][b] 64MB

// ---------------- SMEM layout (u64 units) -----------------------------------
#define WXZ 0
#define WXR 2048
#define WXG 4096
#define WHZ 6144
#define WHR 8192
#define WHG 10240
#define W0Z 12288
#define W0R 12800
#define W0G 13312
#define RED 13824               // 1536 u64 partial buffer
#define SM64_TOTAL 15360
#define SMEM_BYTES (SM64_TOTAL * 8 + 408 * 4)

struct alignas(16) U2 { u64 a, b; };

__device__ __forceinline__ void fma2(u64& c, u64 a, u64 b) {
    asm("fma.rn.f32x2 %0, %1, %2, %0;" : "+l"(c) : "l"(a), "l"(b));
}
__device__ __forceinline__ void add2(u64& c, u64 a) {
    asm("add.rn.f32x2 %0, %0, %1;" : "+l"(c) : "l"(a));
}
__device__ __forceinline__ void pack2(const float4 v, u64& lo, u64& hi) {
    asm("mov.b64 %0, {%1, %2};" : "=l"(lo) : "f"(v.x), "f"(v.y));
    asm("mov.b64 %0, {%1, %2};" : "=l"(hi) : "f"(v.z), "f"(v.w));
}
__device__ __forceinline__ u64 ksred(u64 v) {
    add2(v, __shfl_xor_sync(0xffffffffu, v, 8));
    add2(v, __shfl_xor_sync(0xffffffffu, v, 16));
    return v;
}
__device__ __forceinline__ float sigf(float x) {
    return __fdividef(1.f, 1.f + __expf(-x));
}
__device__ __forceinline__ float tanhfast(float x) {
    return fmaf(2.f, __fdividef(1.f, 1.f + __expf(-2.f * x)), -1.f);
}

// all-CTA barrier: release-arrive + acquire-poll (no full MEMBAR, no sleep)
__device__ __forceinline__ void grid_barrier(unsigned& target) {
    __syncthreads();
    if (threadIdx.x == 0) {
        target += NCTA;
        asm volatile("red.release.gpu.global.add.u32 [%0], 1;"
                     :: "l"(&g_count) : "memory");
        unsigned v;
        do {
            asm volatile("ld.acquire.gpu.global.u32 %0, [%1];"
                         : "=r"(v) : "l"(&g_count) : "memory");
        } while (v < target);
    }
    __syncthreads();
}

// ---------------- init: reset barrier, transpose h0 -------------------------
__global__ void init_kernel(const float* __restrict__ h0) {
    int idx = blockIdx.x * blockDim.x + threadIdx.x;
    if (idx == 0) g_count = 0;
    if (idx < 3 * H_ * B_) {
        int b = idx & 31;
        int k = (idx >> 5) & 511;
        int l = idx >> 14;
        g_h[l][k * 32 + b] = h0[b * (3 * H_) + l * H_ + k];
    }
}

// ---------------- transpose x: [b][t][i] -> [t][i][b] -----------------------
__global__ void transpose_x_kernel(const float* __restrict__ x) {
    __shared__ float tile[32 * 33];
    int t  = blockIdx.x >> 2;
    int i0 = (blockIdx.x & 3) * 32;
    int tid = threadIdx.x;
    int ii = tid & 31, jj = tid >> 5;
    for (int b = jj; b < 32; b += 8)
        tile[b * 33 + ii] = x[((size_t)b * S_ + t) * IN_ + i0 + ii];
    __syncthreads();
    int bb = tid & 31, ir = tid >> 5;
    for (int i = ir; i < 32; i += 8)
        g_xt[(t * IN_ + i0 + i) * B_ + bb] = tile[bb * 33 + i];
}

// ---------------- persistent GRU kernel --------------------------------------
__global__ void __launch_bounds__(NTHR, 1) gru_persistent(
    const float* __restrict__ W0z, const float* __restrict__ b0z,
    const float* __restrict__ W0r, const float* __restrict__ b0r,
    const float* __restrict__ W0g, const float* __restrict__ b0g,
    const float* __restrict__ Wxz, const float* __restrict__ bxz,
    const float* __restrict__ Wxr, const float* __restrict__ bxr,
    const float* __restrict__ Wxg, const float* __restrict__ bxg,
    const float* __restrict__ Whz, const float* __restrict__ Whr,
    const float* __restrict__ Whg)
{
    extern __shared__ u64 sm64[];
    float* tail = (float*)(sm64 + SM64_TOTAL);
    float* s_z = tail;            // [4][32]
    float* s_g = tail + 128;      // [4][32]
    float* s_h = tail + 256;      // [4][32]
    float* s_b = tail + 384;      // [6][4]

    const int tid  = threadIdx.x;
    const int row0 = blockIdx.x * 4;

    // ---- load duplicated weight slices, layout [r][kk][ks] ----
    float2* w2 = (float2*)sm64;
    for (int idx = tid; idx < 2048; idx += NTHR) {
        int r = idx >> 9, kk = (idx >> 5) & 15, kq = idx & 31;
        int g = (row0 + r) * H_ + kq * 16 + kk;
        float w;
        w = Wxz[g]; w2[WXZ + idx] = make_float2(w, w);
        w = Wxr[g]; w2[WXR + idx] = make_float2(w, w);
        w = Wxg[g]; w2[WXG + idx] = make_float2(w, w);
        w = Whz[g]; w2[WHZ + idx] = make_float2(w, w);
        w = Whr[g]; w2[WHR + idx] = make_float2(w, w);
        w = Whg[g]; w2[WHG + idx] = make_float2(w, w);
    }
    for (int idx = tid; idx < 512; idx += NTHR) {
        int r = idx >> 7, kk = (idx >> 5) & 3, kq = idx & 31;
        int g = (row0 + r) * IN_ + kq * 4 + kk;
        float w;
        w = W0z[g]; w2[W0Z + idx] = make_float2(w, w);
        w = W0r[g]; w2[W0R + idx] = make_float2(w, w);
        w = W0g[g]; w2[W0G + idx] = make_float2(w, w);
    }
    if (tid < 4) {
        s_b[0 * 4 + tid] = b0z[row0 + tid];
        s_b[1 * 4 + tid] = b0r[row0 + tid];
        s_b[2 * 4 + tid] = b0g[row0 + tid];
        s_b[3 * 4 + tid] = bxz[row0 + tid];
        s_b[4 * 4 + tid] = bxr[row0 + tid];
        s_b[5 * 4 + tid] = bxg[row0 + tid];
    }
    __syncthreads();

    const int bp   = tid & 7;     // batch quad: b = 4bp .. 4bp+3
    const int ks   = tid >> 3;    // k-slice 0..31 (16 hidden k / 4 input k)
    const int warp = tid >> 5;
    const int lane = tid & 31;
    const int kb   = ks * 16;
    const int kbi  = ks * 4;
    u64* red = sm64 + RED;
    unsigned target = 0;

    for (int t = 0; t < S_; t++) {
        for (int l = 0; l < 3; l++) {
            // ============ phase A: z/r full dots + xg input-side dot =========
            u64 az[4][2], ar[4][2], ag[4][2];
#pragma unroll
            for (int r = 0; r < 4; r++) {
                az[r][0] = az[r][1] = 0ull;
                ar[r][0] = ar[r][1] = 0ull;
                ag[r][0] = ag[r][1] = 0ull;
            }

            if (l == 0) {
                const float4* xin4 = (const float4*)(g_xt + t * (IN_ * B_));
                float4 pfx[4];
#pragma unroll
                for (int kk = 0; kk < 4; kk++)
                    pfx[kk] = __ldcg(xin4 + (kbi + kk) * 8 + bp);
#pragma unroll
                for (int kk = 0; kk < 4; kk++) {
                    u64 x0, x1;
                    pack2(pfx[kk], x0, x1);
#pragma unroll
                    for (int r = 0; r < 4; r++) {
                        int wi = ((r * 4 + kk) << 5) + ks;
                        u64 wz = sm64[W0Z + wi], wr = sm64[W0R + wi], wg = sm64[W0G + wi];
                        fma2(az[r][0], x0, wz); fma2(az[r][1], x1, wz);
                        fma2(ar[r][0], x0, wr); fma2(ar[r][1], x1, wr);
                        fma2(ag[r][0], x0, wg); fma2(ag[r][1], x1, wg);
                    }
                }
                const float4* hin4 = (const float4*)(g_h[0]);
                float4 pfh[3];
#pragma unroll
                for (int i = 0; i < 3; i++)
                    pfh[i] = __ldcg(hin4 + (kb + i) * 8 + bp);
#pragma unroll
                for (int kk = 0; kk < 16; kk++) {
                    u64 h0, h1;
                    pack2(pfh[kk % 3], h0, h1);
                    if (kk < 13)
                        pfh[kk % 3] = __ldcg(hin4 + (kb + kk + 3) * 8 + bp);
#pragma unroll
                    for (int r = 0; r < 4; r++) {
                        int wi = ((r * 16 + kk) << 5) + ks;
                        u64 wz = sm64[WHZ + wi], wr = sm64[WHR + wi];
                        fma2(az[r][0], h0, wz); fma2(az[r][1], h1, wz);
                        fma2(ar[r][0], h0, wr); fma2(ar[r][1], h1, wr);
                    }
                }
            } else {
                const float4* xin4 = (const float4*)(g_h[l - 1]);
                const float4* hin4 = (const float4*)(g_h[l]);
                float4 pfx[3], pfh[3];
#pragma unroll
                for (int i = 0; i < 3; i++) {
                    pfx[i] = __ldcg(xin4 + (kb + i) * 8 + bp);
                    pfh[i] = __ldcg(hin4 + (kb + i) * 8 + bp);
                }
#pragma unroll
                for (int kk = 0; kk < 16; kk++) {
                    u64 x0, x1, h0, h1;
                    pack2(pfx[kk % 3], x0, x1);
                    pack2(pfh[kk % 3], h0, h1);
                    if (kk < 13) {
                        pfx[kk % 3] = __ldcg(xin4 + (kb + kk + 3) * 8 + bp);
                        pfh[kk % 3] = __ldcg(hin4 + (kb + kk + 3) * 8 + bp);
                    }
#pragma unroll
                    for (int r = 0; r < 4; r++) {
                        int wi = ((r * 16 + kk) << 5) + ks;
                        u64 wxzv = sm64[WXZ + wi], wxrv = sm64[WXR + wi];
                        u64 wxgv = sm64[WXG + wi];
                        u64 whzv = sm64[WHZ + wi], whrv = sm64[WHR + wi];
                        fma2(az[r][0], x0, wxzv); fma2(az[r][1], x1, wxzv);
                        fma2(ar[r][0], x0, wxrv); fma2(ar[r][1], x1, wxrv);
                        fma2(ag[r][0], x0, wxgv); fma2(ag[r][1], x1, wxgv);
                        fma2(az[r][0], h0, whzv); fma2(az[r][1], h1, whzv);
                        fma2(ar[r][0], h0, whrv); fma2(ar[r][1], h1, whrv);
                    }
                }
            }
            // in-warp pre-reduction, then STS.128 from lanes 0..7
#pragma unroll
            for (int r = 0; r < 4; r++) {
                u64 vz0 = ksred(az[r][0]), vz1 = ksred(az[r][1]);
                u64 vr0 = ksred(ar[r][0]), vr1 = ksred(ar[r][1]);
                u64 vg0 = ksred(ag[r][0]), vg1 = ksred(ag[r][1]);
                if (lane < 8) {
                    *(U2*)&red[(((0 * 8 + warp) * 4 + r) * 8 + bp) * 2] = U2{vz0, vz1};
                    *(U2*)&red[(((1 * 8 + warp) * 4 + r) * 8 + bp) * 2] = U2{vr0, vr1};
                    *(U2*)&red[(((2 * 8 + warp) * 4 + r) * 8 + bp) * 2] = U2{vg0, vg1};
                }
            }
            __syncthreads();

            // ---- reduce A (256 threads: 2 per item): z, r; publish r*h ----
            {
                int item = tid >> 1, half = tid & 1;
                int r = item >> 5, b = item & 31;
                const float* rf = (const float*)red;
                int w0 = half * 4;
                float sz_ = 0.f, sr_ = 0.f, sg_ = 0.f;
#pragma unroll
                for (int w = 0; w < 4; w++) {
                    sz_ += rf[(0 * 8 + w0 + w) * 128 + r * 32 + b];
                    sr_ += rf[(1 * 8 + w0 + w) * 128 + r * 32 + b];
                    sg_ += rf[(2 * 8 + w0 + w) * 128 + r * 32 + b];
                }
                sz_ += __shfl_xor_sync(0xffffffffu, sz_, 1);
                sr_ += __shfl_xor_sync(0xffffffffu, sr_, 1);
                sg_ += __shfl_xor_sync(0xffffffffu, sg_, 1);
                if (half == 0) {
                    int bb = (l == 0) ? 0 : 3;
                    float zv = sigf(sz_ + s_b[bb * 4 + r]);
                    float rv = sigf(sr_ + s_b[(bb + 1) * 4 + r]);
                    float hold = __ldcg(&g_h[l][(row0 + r) * 32 + b]);
                    __stcg(&g_rh[(row0 + r) * 32 + b], rv * hold);
                    s_z[item] = zv;
                    s_g[item] = sg_ + s_b[(bb + 2) * 4 + r];
                    s_h[item] = hold;
                }
            }
            grid_barrier(target);

            // ============ phase B: (r*h) @ Whg^T =============================
            {
                u64 agg[4][2];
#pragma unroll
                for (int r = 0; r < 4; r++) agg[r][0] = agg[r][1] = 0ull;
                const float4* rin4 = (const float4*)g_rh;
                float4 pfr[3];
#pragma unroll
                for (int i = 0; i < 3; i++)
                    pfr[i] = __ldcg(rin4 + (kb + i) * 8 + bp);
#pragma unroll
                for (int kk = 0; kk < 16; kk++) {
                    u64 v0, v1;
                    pack2(pfr[kk % 3], v0, v1);
                    if (kk < 13)
                        pfr[kk % 3] = __ldcg(rin4 + (kb + kk + 3) * 8 + bp);
#pragma unroll
                    for (int r = 0; r < 4; r++) {
                        u64 wg = sm64[WHG + ((r * 16 + kk) << 5) + ks];
                        fma2(agg[r][0], v0, wg); fma2(agg[r][1], v1, wg);
                    }
                }
#pragma unroll
                for (int r = 0; r < 4; r++) {
                    u64 v0 = ksred(agg[r][0]), v1 = ksred(agg[r][1]);
                    if (lane < 8)
                        *(U2*)&red[((warp * 4 + r) * 8 + bp) * 2] = U2{v0, v1};
                }
            }
            __syncthreads();

            // ---- reduce B (256 threads: 2 per item): g, h_new ----
            {
                int item = tid >> 1, half = tid & 1;
                int r = item >> 5, b = item & 31;
                const float* rf = (const float*)red;
                int w0 = half * 4;
                float s = 0.f;
#pragma unroll
                for (int w = 0; w < 4; w++)
                    s += rf[(w0 + w) * 128 + r * 32 + b];
                s += __shfl_xor_sync(0xffffffffu, s, 1);
                if (half == 0) {
                    float gv = tanhfast(s_g[item] + s);
                    float hn = fmaf(s_z[item], s_h[item] - gv, gv);
                    __stcg(&g_h[l][(row0 + r) * 32 + b], hn);
                    if (l == 2)
                        g_hist[(size_t)t * (H_ * B_) + (row0 + r) * 32 + b] = hn;
                }
            }
            grid_barrier(target);
        }
    }
}

// ---------------- epilogue: out = hist @ Wout^T + bout ----------------------
__global__ void __launch_bounds__(256) out_proj_kernel(
    const float* __restrict__ Wout, const float* __restrict__ bout,
    float* __restrict__ out)
{
    extern __shared__ float sh[];   // 64 KB: hist[t]
    int t = blockIdx.x;
    int tid = threadIdx.x;
    const float* src = g_hist + (size_t)t * (H_ * B_);
    for (int j = tid; j < (H_ * B_) / 4; j += 256)
        ((float4*)sh)[j] = ((const float4*)src)[j];
    __syncthreads();

    int o0 = (tid >> 3) * 4;
    int b0 = (tid & 7) * 4;
    float acc[4][4];
#pragma unroll
    for (int i = 0; i < 4; i++)
#pragma unroll
        for (int j = 0; j < 4; j++) acc[i][j] = 0.f;

    for (int k = 0; k < H_; k += 4) {
        float4 h0 = *(const float4*)&sh[(k + 0) * 32 + b0];
        float4 h1 = *(const float4*)&sh[(k + 1) * 32 + b0];
        float4 h2 = *(const float4*)&sh[(k + 2) * 32 + b0];
        float4 h3 = *(const float4*)&sh[(k + 3) * 32 + b0];
#pragma unroll
        for (int i = 0; i < 4; i++) {
            float4 w = __ldg((const float4*)&Wout[(o0 + i) * H_ + k]);
            acc[i][0] = fmaf(w.x, h0.x, acc[i][0]);
            acc[i][0] = fmaf(w.y, h1.x, acc[i][0]);
            acc[i][0] = fmaf(w.z, h2.x, acc[i][0]);
            acc[i][0] = fmaf(w.w, h3.x, acc[i][0]);
            acc[i][1] = fmaf(w.x, h0.y, acc[i][1]);
            acc[i][1] = fmaf(w.y, h1.y, acc[i][1]);
            acc[i][1] = fmaf(w.z, h2.y, acc[i][1]);
            acc[i][1] = fmaf(w.w, h3.y, acc[i][1]);
            acc[i][2] = fmaf(w.x, h0.z, acc[i][2]);
            acc[i][2] = fmaf(w.y, h1.z, acc[i][2]);
            acc[i][2] = fmaf(w.z, h2.z, acc[i][2]);
            acc[i][2] = fmaf(w.w, h3.z, acc[i][2]);
            acc[i][3] = fmaf(w.x, h0.w, acc[i][3]);
            acc[i][3] = fmaf(w.y, h1.w, acc[i][3]);
            acc[i][3] = fmaf(w.z, h2.w, acc[i][3]);
            acc[i][3] = fmaf(w.w, h3.w, acc[i][3]);
        }
    }
#pragma unroll
    for (int j = 0; j < 4; j++)
#pragma unroll
        for (int i = 0; i < 4; i++)
            out[((size_t)(b0 + j) * S_ + t) * OUT_ + o0 + i] =
                acc[i][j] + __ldg(&bout[o0 + i]);
}

// ---------------- epilogue: final hidden state (B, L, H) --------------------
__global__ void final_state_kernel(float* __restrict__ out2) {
    int idx = blockIdx.x * blockDim.x + threadIdx.x;
    if (idx < 3 * H_ * B_) {
        int k = idx & 511;
        int v = idx >> 9;
        int l = v % 3;
        int b = v / 3;
        out2[idx] = g_h[l][k * 32 + b];
    }
}

// ---------------- launch ----------------------------------------------------
extern "C" void kernel_launch(void* const* d_in, const int* in_sizes, int n_in,
                              void* d_out, int out_size) {
    const float* x    = (const float*)d_in[0];
    const float* h0   = (const float*)d_in[1];
    const float* W0z  = (const float*)d_in[2];
    const float* b0z  = (const float*)d_in[3];
    const float* W0r  = (const float*)d_in[4];
    const float* b0r  = (const float*)d_in[5];
    const float* W0g  = (const float*)d_in[6];
    const float* b0g  = (const float*)d_in[7];
    const float* Wxz  = (const float*)d_in[8];
    const float* bxz  = (const float*)d_in[9];
    const float* Wxr  = (const float*)d_in[10];
    const float* bxr  = (const float*)d_in[11];
    const float* Wxg  = (const float*)d_in[12];
    const float* bxg  = (const float*)d_in[13];
    const float* Whz  = (const float*)d_in[14];
    const float* Whr  = (const float*)d_in[15];
    const float* Whg  = (const float*)d_in[16];
    const float* Wout = (const float*)d_in[17];
    const float* bout = (const float*)d_in[18];
    float* out = (float*)d_out;

    cudaFuncSetAttribute(gru_persistent,
                         cudaFuncAttributeMaxDynamicSharedMemorySize, SMEM_BYTES);
    cudaFuncSetAttribute(out_proj_kernel,
                         cudaFuncAttributeMaxDynamicSharedMemorySize, 65536);

    init_kernel<<<192, 256>>>(h0);
    transpose_x_kernel<<<S_ * 4, 256>>>(x);
    gru_persistent<<<NCTA, NTHR, SMEM_BYTES>>>(
        W0z, b0z, W0r, b0r, W0g, b0g,
        Wxz, bxz, Wxr, bxr, Wxg, bxg,
        Whz, Whr, Whg);
    out_proj_kernel<<<S_, 256, 65536>>>(Wout, bout, out);
    final_state_kernel<<<192, 256>>>(out + (size_t)B_ * S_ * OUT_);
}